// round 12
// baseline (speedup 1.0000x reference)
#include <cuda_runtime.h>
#include <cuda_fp16.h>
#include <math.h>

typedef unsigned int u32;

#define ALPHA   8.3f
#define C_IN    64
#define C_OUT   64
#define H_IN    256
#define W_IN    256
#define H_OUT   254
#define W_OUT   254

#define NTHREADS 256
#define TILES_PER_BATCH (127 * 4)   // 127 p-pairs x 4 q-tiles of 64
#define NTILES   (4 * TILES_PER_BATCH)

#define PIXN     264                 // 4 rows x 66 cols
#define SLOTSTR  268                 // u64 stride per slot (bank-safe: 24t mod 32)
// ---- smem layout (bytes) ----
#define OFF_BIAS 0                   // 64 f                = 256
#define OFF_D    256                 // 4 x 66 f            = 1056
#define OFF_DW   1312                // 9 x 128 f           = 4608
#define OFF_IMGH 5920                // 16 slots x 268 u64  = 34304
#define SMEM_TOTAL 40224

__device__ __forceinline__ u32 packh2(float lo, float hi) {
    u32 r;
    asm("cvt.rn.f16x2.f32 %0, %1, %2;" : "=r"(r) : "f"(hi), "f"(lo));
    return r;
}
__device__ __forceinline__ u32 hmul2(u32 a, u32 b) {
    u32 r;
    asm("mul.rn.f16x2 %0, %1, %2;" : "=r"(r) : "r"(a), "r"(b));
    return r;
}

// mma.sync m16n8k16 fp16: D(16x8,f32) += A(16x16,f16) * B(16x8,f16)
#define MMA_F16(d, a0, a1, a2, a3, b0, b1)                                  \
    asm volatile(                                                           \
        "mma.sync.aligned.m16n8k16.row.col.f32.f16.f16.f32 "                \
        "{%0,%1,%2,%3}, {%4,%5,%6,%7}, {%8,%9}, {%0,%1,%2,%3};"             \
        : "+f"((d)[0]), "+f"((d)[1]), "+f"((d)[2]), "+f"((d)[3])            \
        : "r"(a0), "r"(a1), "r"(a2), "r"(a3), "r"(b0), "r"(b1))

// W pre-packed fp16 B-fragments: [kc16(36)][j(4)][lane(32)] uint4.
__device__ __align__(16) uint4 g_wh[36 * 4 * 32];

__global__ void prep_w(const float* __restrict__ w) {
    int idx = blockIdx.x * blockDim.x + threadIdx.x;
    if (idx >= 36 * 4 * 32) return;
    int lane = idx & 31;
    int j    = (idx >> 5) & 3;
    int kc16 = idx >> 7;
    int kl = kc16 >> 2, cq = kc16 & 3;
    int g = lane >> 2, t = lane & 3;
    int c0 = cq * 16 + 2 * t;
    int oce = (2 * j) * 8 + g;
    int oco = oce + 8;
    uint4 v;
    v.x = packh2(w[(oce * C_IN + c0)     * 9 + kl], w[(oce * C_IN + c0 + 1) * 9 + kl]);
    v.y = packh2(w[(oce * C_IN + c0 + 8) * 9 + kl], w[(oce * C_IN + c0 + 9) * 9 + kl]);
    v.z = packh2(w[(oco * C_IN + c0)     * 9 + kl], w[(oco * C_IN + c0 + 1) * 9 + kl]);
    v.w = packh2(w[(oco * C_IN + c0 + 8) * 9 + kl], w[(oco * C_IN + c0 + 9) * 9 + kl]);
    g_wh[idx] = v;
}

__global__ __launch_bounds__(NTHREADS, 4)
void depthconv_mma(const float* __restrict__ img,
                   const float* __restrict__ depth,
                   const float* __restrict__ bias,
                   float* __restrict__ out) {
    extern __shared__ char smem[];
    float* s_b    = (float*)(smem + OFF_BIAS);
    float* s_d    = (float*)(smem + OFF_D);
    float* s_dw   = (float*)(smem + OFF_DW);
    uint2* s_imgh = (uint2*)(smem + OFF_IMGH);   // [slot(16)][pix], stride SLOTSTR

    const int tid  = threadIdx.x;
    const int lane = tid & 31;
    const int wid  = tid >> 5;          // 8 warps: each 16 M-pixels x 64 oc
    const int g    = lane >> 2;
    const int t    = lane & 3;
    const int pr   = wid >> 2;          // output row within p-pair
    const int qw   = (wid & 3) * 16;    // q base of this warp's strip

    const int tIdx = blockIdx.x;
    const int b  = tIdx / TILES_PER_BATCH;
    const int r  = tIdx - b * TILES_PER_BATCH;
    const int p0 = (r >> 2) << 1;       // 0..252
    const int q0 = (r & 3) << 6;
    const int qcnt = min(64, W_OUT - q0);

    // ---- stage bias + depth halo (4 x 66) ----
    if (tid < C_OUT) s_b[tid] = bias[tid];
    for (int i = tid; i < 264; i += NTHREADS) {
        int rr = i / 66, cc = i - rr * 66;
        s_d[i] = depth[(size_t)b * H_IN * W_IN + (p0 + rr) * W_IN +
                       min(q0 + cc, W_IN - 1)];
    }
    // ---- stage img as paired fp16x2: slot = cq*4+t holds (cpair t, cpair t+4) ----
    {
        const float* ip = img + (size_t)b * C_IN * H_IN * W_IN;
        for (int i = tid; i < 16 * PIXN; i += NTHREADS) {
            int slot = i / PIXN;
            int pix  = i - slot * PIXN;
            int cq   = slot >> 2, tt = slot & 3;
            int ch0  = (cq * 8 + tt) * 2;          // channels ch0, ch0+1
            int rr   = pix / 66, cc = pix - rr * 66;
            size_t go = ((size_t)ch0 * H_IN + (p0 + rr)) * W_IN +
                        min(q0 + cc, W_IN - 1);
            const size_t HW = (size_t)H_IN * W_IN;
            uint2 v;
            v.x = packh2(ip[go],          ip[go + HW]);       // ch0, ch0+1
            v.y = packh2(ip[go + 8 * HW], ip[go + 9 * HW]);   // ch0+8, ch0+9
            s_imgh[slot * SLOTSTR + pix] = v;
        }
    }
    __syncthreads();
    // ---- dw[kl][m] (channel-independent) ----
    for (int i = tid; i < 1152; i += NTHREADS) {
        int kl = i >> 7, m = i & 127;
        int mpr = m >> 6, qq = m & 63;
        int k = kl / 3, l = kl - k * 3;
        float cen = s_d[(mpr + 1) * 66 + qq + 1];
        s_dw[i] = __expf(-ALPHA * fabsf(s_d[(mpr + k) * 66 + qq + l] - cen));
    }
    __syncthreads();

    float acc[8][4];
#pragma unroll
    for (int nb = 0; nb < 8; nb++)
#pragma unroll
        for (int rr = 0; rr < 4; rr++) acc[nb][rr] = 0.f;

    // ---- K loop: kl outer (not unrolled), cq inner x4 (16 channels each) ----
    const uint4* wlane = g_wh + lane;
    for (int k = 0; k < 3; k++) {
#pragma unroll 1
        for (int l = 0; l < 3; l++) {
            const int kl = k * 3 + l;
            const float* dwp = s_dw + kl * 128 + pr * 64 + qw;
            const u32 dwh0 = packh2(dwp[g],     dwp[g]);
            const u32 dwh1 = packh2(dwp[g + 8], dwp[g + 8]);
            const int pixbase = (pr + k) * 66 + l + qw;

#pragma unroll
            for (int cq = 0; cq < 4; cq++) {
                const uint4* wf = wlane + (size_t)(kl * 4 + cq) * 128;
                const uint2* pc = s_imgh + (cq * 4 + t) * SLOTSTR + pixbase;

                // A: 2 x LDS.64 -> (a0,a2) at pix g, (a1,a3) at pix g+8
                uint2 va = pc[g];
                uint2 vb = pc[g + 8];
                u32 a0 = hmul2(va.x, dwh0);
                u32 a2 = hmul2(va.y, dwh0);
                u32 a1 = hmul2(vb.x, dwh1);
                u32 a3 = hmul2(vb.y, dwh1);

                // B half 1 + 4 MMAs, then half 2 + 4 MMAs (keeps B live regs = 8)
                uint4 bq0 = __ldg(wf);
                uint4 bq1 = __ldg(wf + 32);
                MMA_F16(acc[0], a0, a1, a2, a3, bq0.x, bq0.y);
                MMA_F16(acc[1], a0, a1, a2, a3, bq0.z, bq0.w);
                MMA_F16(acc[2], a0, a1, a2, a3, bq1.x, bq1.y);
                MMA_F16(acc[3], a0, a1, a2, a3, bq1.z, bq1.w);
                uint4 bq2 = __ldg(wf + 64);
                uint4 bq3 = __ldg(wf + 96);
                MMA_F16(acc[4], a0, a1, a2, a3, bq2.x, bq2.y);
                MMA_F16(acc[5], a0, a1, a2, a3, bq2.z, bq2.w);
                MMA_F16(acc[6], a0, a1, a2, a3, bq3.x, bq3.y);
                MMA_F16(acc[7], a0, a1, a2, a3, bq3.z, bq3.w);
            }
        }
    }

    // ---- epilogue: bias + store ----
    const int qq0 = qw + g;
#pragma unroll
    for (int nb = 0; nb < 8; nb++) {
        const int oc = nb * 8 + t * 2;
        const float bs0 = s_b[oc], bs1 = s_b[oc + 1];
        const size_t base =
            (((size_t)b * C_OUT + oc) * H_OUT + (p0 + pr)) * W_OUT + q0;
        if (qq0 < qcnt) {
            out[base + qq0]                         = acc[nb][0] + bs0;
            out[base + (size_t)H_OUT * W_OUT + qq0] = acc[nb][1] + bs1;
        }
        if (qq0 + 8 < qcnt) {
            out[base + qq0 + 8]                         = acc[nb][2] + bs0;
            out[base + (size_t)H_OUT * W_OUT + qq0 + 8] = acc[nb][3] + bs1;
        }
    }
}

extern "C" void kernel_launch(void* const* d_in, const int* in_sizes, int n_in,
                              void* d_out, int out_size) {
    const float* img    = nullptr;
    const float* depth  = nullptr;
    const float* weight = nullptr;
    const float* bias   = nullptr;

    for (int i = 0; i < n_in; i++) {
        switch (in_sizes[i]) {
            case 4 * C_IN * H_IN * W_IN: img    = (const float*)d_in[i]; break;
            case 4 * 1 * H_IN * W_IN:    depth  = (const float*)d_in[i]; break;
            case C_OUT * C_IN * 9:       weight = (const float*)d_in[i]; break;
            case C_OUT:                  bias   = (const float*)d_in[i]; break;
            default: break;
        }
    }

    cudaFuncSetAttribute(depthconv_mma,
                         cudaFuncAttributeMaxDynamicSharedMemorySize, SMEM_TOTAL);

    prep_w<<<(36 * 4 * 32 + 255) / 256, 256>>>(weight);
    depthconv_mma<<<NTILES, NTHREADS, SMEM_TOTAL>>>(img, depth, bias, (float*)d_out);
}

// round 13
// speedup vs baseline: 1.0156x; 1.0156x over previous
#include <cuda_runtime.h>
#include <cuda_fp16.h>
#include <math.h>

typedef unsigned int u32;

#define ALPHA   8.3f
#define C_IN    64
#define C_OUT   64
#define H_IN    256
#define W_IN    256
#define H_OUT   254
#define W_OUT   254

#define NTHREADS 256
#define TILES_PER_BATCH (127 * 4)   // 127 p-pairs x 4 q-tiles of 64
#define NTILES   (4 * TILES_PER_BATCH)

#define PIXN     264                 // 4 rows x 66 cols
#define SLOTSTR  268                 // u64 stride per slot (bank-safe)
// ---- smem layout (bytes) ----
#define OFF_BIAS 0                   // 64 f                = 256
#define OFF_D    256                 // 4 x 66 f            = 1056
#define OFF_DW   1312                // 9 x 128 f           = 4608
#define OFF_IMGH 5920                // 16 slots x 268 u64  = 34304
#define SMEM_TOTAL 40224

__device__ __forceinline__ u32 packh2(float lo, float hi) {
    u32 r;
    asm("cvt.rn.f16x2.f32 %0, %1, %2;" : "=r"(r) : "f"(hi), "f"(lo));
    return r;
}
__device__ __forceinline__ u32 hmul2(u32 a, u32 b) {
    u32 r;
    asm("mul.rn.f16x2 %0, %1, %2;" : "=r"(r) : "r"(a), "r"(b));
    return r;
}

// mma.sync m16n8k16 fp16: D(16x8,f32) += A(16x16,f16) * B(16x8,f16)
#define MMA_F16(d, a0, a1, a2, a3, b0, b1)                                  \
    asm volatile(                                                           \
        "mma.sync.aligned.m16n8k16.row.col.f32.f16.f16.f32 "                \
        "{%0,%1,%2,%3}, {%4,%5,%6,%7}, {%8,%9}, {%0,%1,%2,%3};"             \
        : "+f"((d)[0]), "+f"((d)[1]), "+f"((d)[2]), "+f"((d)[3])            \
        : "r"(a0), "r"(a1), "r"(a2), "r"(a3), "r"(b0), "r"(b1))

// W pre-packed fp16 B-fragments: [kc16(36)][j(4)][lane(32)] uint4.
__device__ __align__(16) uint4 g_wh[36 * 4 * 32];

__global__ void prep_w(const float* __restrict__ w) {
    int idx = blockIdx.x * blockDim.x + threadIdx.x;
    if (idx >= 36 * 4 * 32) return;
    int lane = idx & 31;
    int j    = (idx >> 5) & 3;
    int kc16 = idx >> 7;
    int kl = kc16 >> 2, cq = kc16 & 3;
    int g = lane >> 2, t = lane & 3;
    int c0 = cq * 16 + 2 * t;
    int oce = (2 * j) * 8 + g;
    int oco = oce + 8;
    uint4 v;
    v.x = packh2(w[(oce * C_IN + c0)     * 9 + kl], w[(oce * C_IN + c0 + 1) * 9 + kl]);
    v.y = packh2(w[(oce * C_IN + c0 + 8) * 9 + kl], w[(oce * C_IN + c0 + 9) * 9 + kl]);
    v.z = packh2(w[(oco * C_IN + c0)     * 9 + kl], w[(oco * C_IN + c0 + 1) * 9 + kl]);
    v.w = packh2(w[(oco * C_IN + c0 + 8) * 9 + kl], w[(oco * C_IN + c0 + 9) * 9 + kl]);
    g_wh[idx] = v;
}

__global__ __launch_bounds__(NTHREADS, 3)
void depthconv_mma(const float* __restrict__ img,
                   const float* __restrict__ depth,
                   const float* __restrict__ bias,
                   float* __restrict__ out) {
    extern __shared__ char smem[];
    float* s_b    = (float*)(smem + OFF_BIAS);
    float* s_d    = (float*)(smem + OFF_D);
    float* s_dw   = (float*)(smem + OFF_DW);
    uint2* s_imgh = (uint2*)(smem + OFF_IMGH);   // [slot(16)][pix], stride SLOTSTR

    const int tid  = threadIdx.x;
    const int lane = tid & 31;
    const int wid  = tid >> 5;          // 8 warps: each 16 M-pixels x 64 oc
    const int g    = lane >> 2;
    const int t    = lane & 3;
    const int pr   = wid >> 2;          // output row within p-pair
    const int qw   = (wid & 3) * 16;    // q base of this warp's strip

    const int tIdx = blockIdx.x;
    const int b  = tIdx / TILES_PER_BATCH;
    const int r  = tIdx - b * TILES_PER_BATCH;
    const int p0 = (r >> 2) << 1;       // 0..252
    const int q0 = (r & 3) << 6;
    const int qcnt = min(64, W_OUT - q0);

    // ---- stage bias + depth halo (4 x 66) ----
    if (tid < C_OUT) s_b[tid] = bias[tid];
    for (int i = tid; i < 264; i += NTHREADS) {
        int rr = i / 66, cc = i - rr * 66;
        s_d[i] = depth[(size_t)b * H_IN * W_IN + (p0 + rr) * W_IN +
                       min(q0 + cc, W_IN - 1)];
    }
    // ---- stage img as paired fp16x2: slot = cq*4+t holds (cpair t, cpair t+4) ----
    {
        const float* ip = img + (size_t)b * C_IN * H_IN * W_IN;
        for (int i = tid; i < 16 * PIXN; i += NTHREADS) {
            int slot = i / PIXN;
            int pix  = i - slot * PIXN;
            int cq   = slot >> 2, tt = slot & 3;
            int ch0  = (cq * 8 + tt) * 2;          // channels ch0, ch0+1
            int rr   = pix / 66, cc = pix - rr * 66;
            size_t go = ((size_t)ch0 * H_IN + (p0 + rr)) * W_IN +
                        min(q0 + cc, W_IN - 1);
            const size_t HW = (size_t)H_IN * W_IN;
            uint2 v;
            v.x = packh2(ip[go],          ip[go + HW]);       // ch0, ch0+1
            v.y = packh2(ip[go + 8 * HW], ip[go + 9 * HW]);   // ch0+8, ch0+9
            s_imgh[slot * SLOTSTR + pix] = v;
        }
    }
    __syncthreads();
    // ---- dw[kl][m] (channel-independent) ----
    for (int i = tid; i < 1152; i += NTHREADS) {
        int kl = i >> 7, m = i & 127;
        int mpr = m >> 6, qq = m & 63;
        int k = kl / 3, l = kl - k * 3;
        float cen = s_d[(mpr + 1) * 66 + qq + 1];
        s_dw[i] = __expf(-ALPHA * fabsf(s_d[(mpr + k) * 66 + qq + l] - cen));
    }
    __syncthreads();

    float acc[8][4];
#pragma unroll
    for (int nb = 0; nb < 8; nb++)
#pragma unroll
        for (int rr = 0; rr < 4; rr++) acc[nb][rr] = 0.f;

    // ---- K loop: kl outer (not unrolled), cq inner x4 (16 channels each) ----
    const uint4* wlane = g_wh + lane;
    for (int k = 0; k < 3; k++) {
#pragma unroll 1
        for (int l = 0; l < 3; l++) {
            const int kl = k * 3 + l;
            const float* dwp = s_dw + kl * 128 + pr * 64 + qw;
            const u32 dwh0 = packh2(dwp[g],     dwp[g]);
            const u32 dwh1 = packh2(dwp[g + 8], dwp[g + 8]);
            const int pixbase = (pr + k) * 66 + l + qw;

#pragma unroll
            for (int cq = 0; cq < 4; cq++) {
                const uint4* wf = wlane + (size_t)(kl * 4 + cq) * 128;
                uint4 bq0 = __ldg(wf);
                uint4 bq1 = __ldg(wf + 32);
                uint4 bq2 = __ldg(wf + 64);
                uint4 bq3 = __ldg(wf + 96);

                const uint2* pc = s_imgh + (cq * 4 + t) * SLOTSTR + pixbase;
                // A: 2 x LDS.64 -> (a0,a2) at pix g, (a1,a3) at pix g+8
                uint2 va = pc[g];
                uint2 vb = pc[g + 8];
                u32 a0 = hmul2(va.x, dwh0);
                u32 a2 = hmul2(va.y, dwh0);
                u32 a1 = hmul2(vb.x, dwh1);
                u32 a3 = hmul2(vb.y, dwh1);

                MMA_F16(acc[0], a0, a1, a2, a3, bq0.x, bq0.y);
                MMA_F16(acc[1], a0, a1, a2, a3, bq0.z, bq0.w);
                MMA_F16(acc[2], a0, a1, a2, a3, bq1.x, bq1.y);
                MMA_F16(acc[3], a0, a1, a2, a3, bq1.z, bq1.w);
                MMA_F16(acc[4], a0, a1, a2, a3, bq2.x, bq2.y);
                MMA_F16(acc[5], a0, a1, a2, a3, bq2.z, bq2.w);
                MMA_F16(acc[6], a0, a1, a2, a3, bq3.x, bq3.y);
                MMA_F16(acc[7], a0, a1, a2, a3, bq3.z, bq3.w);
            }
        }
    }

    // ---- epilogue: bias + store ----
    const int qq0 = qw + g;
#pragma unroll
    for (int nb = 0; nb < 8; nb++) {
        const int oc = nb * 8 + t * 2;
        const float bs0 = s_b[oc], bs1 = s_b[oc + 1];
        const size_t base =
            (((size_t)b * C_OUT + oc) * H_OUT + (p0 + pr)) * W_OUT + q0;
        if (qq0 < qcnt) {
            out[base + qq0]                         = acc[nb][0] + bs0;
            out[base + (size_t)H_OUT * W_OUT + qq0] = acc[nb][1] + bs1;
        }
        if (qq0 + 8 < qcnt) {
            out[base + qq0 + 8]                         = acc[nb][2] + bs0;
            out[base + (size_t)H_OUT * W_OUT + qq0 + 8] = acc[nb][3] + bs1;
        }
    }
}

extern "C" void kernel_launch(void* const* d_in, const int* in_sizes, int n_in,
                              void* d_out, int out_size) {
    const float* img    = nullptr;
    const float* depth  = nullptr;
    const float* weight = nullptr;
    const float* bias   = nullptr;

    for (int i = 0; i < n_in; i++) {
        switch (in_sizes[i]) {
            case 4 * C_IN * H_IN * W_IN: img    = (const float*)d_in[i]; break;
            case 4 * 1 * H_IN * W_IN:    depth  = (const float*)d_in[i]; break;
            case C_OUT * C_IN * 9:       weight = (const float*)d_in[i]; break;
            case C_OUT:                  bias   = (const float*)d_in[i]; break;
            default: break;
        }
    }

    cudaFuncSetAttribute(depthconv_mma,
                         cudaFuncAttributeMaxDynamicSharedMemorySize, SMEM_TOTAL);

    prep_w<<<(36 * 4 * 32 + 255) / 256, 256>>>(weight);
    depthconv_mma<<<NTILES, NTHREADS, SMEM_TOTAL>>>(img, depth, bias, (float*)d_out);
}

// round 14
// speedup vs baseline: 1.0280x; 1.0121x over previous
#include <cuda_runtime.h>
#include <cuda_fp16.h>
#include <math.h>

typedef unsigned int u32;

#define ALPHA   8.3f
#define C_IN    64
#define C_OUT   64
#define H_IN    256
#define W_IN    256
#define H_OUT   254
#define W_OUT   254

#define NTHREADS 128
#define TILES_PER_BATCH (254 * 4)   // 254 p-rows x 4 q-tiles of 64
#define NTILES   (4 * TILES_PER_BATCH)

#define PIXW     198                 // 3 rows x 66 cols
#define CPSTR    200                 // u32 stride per cpair (t offsets {0,8,16,24} banks)
// ---- smem layout (bytes) ----
#define OFF_BIAS 0                   // 64 f               = 256
#define OFF_D    256                 // 3 x 66 f           = 792 (pad to 800)
#define OFF_DW   1056                // 9 x 64 f           = 2304
#define OFF_IMGH 3360                // 32 cpair x 200 u32 = 25600
#define SMEM_TOTAL 28960

__device__ __forceinline__ u32 packh2(float lo, float hi) {
    u32 r;
    asm("cvt.rn.f16x2.f32 %0, %1, %2;" : "=r"(r) : "f"(hi), "f"(lo));
    return r;
}
__device__ __forceinline__ u32 hmul2(u32 a, u32 b) {
    u32 r;
    asm("mul.rn.f16x2 %0, %1, %2;" : "=r"(r) : "r"(a), "r"(b));
    return r;
}

// mma.sync m16n8k16 fp16: D(16x8,f32) += A(16x16,f16) * B(16x8,f16)
#define MMA_F16(d, a0, a1, a2, a3, b0, b1)                                  \
    asm volatile(                                                           \
        "mma.sync.aligned.m16n8k16.row.col.f32.f16.f16.f32 "                \
        "{%0,%1,%2,%3}, {%4,%5,%6,%7}, {%8,%9}, {%0,%1,%2,%3};"             \
        : "+f"((d)[0]), "+f"((d)[1]), "+f"((d)[2]), "+f"((d)[3])            \
        : "r"(a0), "r"(a1), "r"(a2), "r"(a3), "r"(b0), "r"(b1))

// W pre-packed fp16 B-fragments: [kc16(36)][j(4)][lane(32)] uint4.
__device__ __align__(16) uint4 g_wh[36 * 4 * 32];

__global__ void prep_w(const float* __restrict__ w) {
    int idx = blockIdx.x * blockDim.x + threadIdx.x;
    if (idx >= 36 * 4 * 32) return;
    int lane = idx & 31;
    int j    = (idx >> 5) & 3;
    int kc16 = idx >> 7;
    int kl = kc16 >> 2, cq = kc16 & 3;
    int g = lane >> 2, t = lane & 3;
    int c0 = cq * 16 + 2 * t;
    int oce = (2 * j) * 8 + g;
    int oco = oce + 8;
    uint4 v;
    v.x = packh2(w[(oce * C_IN + c0)     * 9 + kl], w[(oce * C_IN + c0 + 1) * 9 + kl]);
    v.y = packh2(w[(oce * C_IN + c0 + 8) * 9 + kl], w[(oce * C_IN + c0 + 9) * 9 + kl]);
    v.z = packh2(w[(oco * C_IN + c0)     * 9 + kl], w[(oco * C_IN + c0 + 1) * 9 + kl]);
    v.w = packh2(w[(oco * C_IN + c0 + 8) * 9 + kl], w[(oco * C_IN + c0 + 9) * 9 + kl]);
    g_wh[idx] = v;
}

__global__ __launch_bounds__(NTHREADS, 5)
void depthconv_mma(const float* __restrict__ img,
                   const float* __restrict__ depth,
                   const float* __restrict__ bias,
                   float* __restrict__ out) {
    extern __shared__ char smem[];
    float* s_b    = (float*)(smem + OFF_BIAS);
    float* s_d    = (float*)(smem + OFF_D);
    float* s_dw   = (float*)(smem + OFF_DW);
    u32*   s_imgh = (u32*)  (smem + OFF_IMGH);   // [cpair(32)][pix], stride CPSTR

    const int tid  = threadIdx.x;
    const int lane = tid & 31;
    const int wid  = tid >> 5;          // 4 warps: each 16 q-pixels x 64 oc
    const int g    = lane >> 2;
    const int t    = lane & 3;
    const int qw   = wid * 16;          // q base of this warp's strip

    const int tIdx = blockIdx.x;
    const int b  = tIdx / TILES_PER_BATCH;
    const int r  = tIdx - b * TILES_PER_BATCH;
    const int p0 = r >> 2;              // 0..253
    const int q0 = (r & 3) << 6;
    const int qcnt = min(64, W_OUT - q0);

    // ---- stage bias + depth halo (3 x 66) ----
    if (tid < C_OUT) s_b[tid] = bias[tid];
    for (int i = tid; i < 3 * 66; i += NTHREADS) {
        int rr = i / 66, cc = i - rr * 66;
        s_d[i] = depth[(size_t)b * H_IN * W_IN + (p0 + rr) * W_IN +
                       min(q0 + cc, W_IN - 1)];
    }
    // ---- stage img as fp16x2 channel pairs: s_imgh[cpair][pix] ----
    {
        const float* ip = img + (size_t)b * C_IN * H_IN * W_IN;
        const size_t HW = (size_t)H_IN * W_IN;
        for (int i = tid; i < 32 * PIXW; i += NTHREADS) {
            int cp  = i / PIXW;
            int pix = i - cp * PIXW;
            int rr  = pix / 66, cc = pix - rr * 66;
            size_t go = ((size_t)(2 * cp) * H_IN + (p0 + rr)) * W_IN +
                        min(q0 + cc, W_IN - 1);
            s_imgh[cp * CPSTR + pix] = packh2(ip[go], ip[go + HW]);
        }
    }
    __syncthreads();
    // ---- dw[kl][qq] (channel-independent, single output row) ----
    for (int i = tid; i < 9 * 64; i += NTHREADS) {
        int kl = i >> 6, qq = i & 63;
        int k = kl / 3, l = kl - k * 3;
        float cen = s_d[66 + qq + 1];
        s_dw[i] = __expf(-ALPHA * fabsf(s_d[k * 66 + qq + l] - cen));
    }
    __syncthreads();

    float acc[8][4];
#pragma unroll
    for (int nb = 0; nb < 8; nb++)
#pragma unroll
        for (int rr = 0; rr < 4; rr++) acc[nb][rr] = 0.f;

    // ---- K loop: kl outer (not unrolled), cq inner x4 with B double-buffer ----
    const uint4* wlane = g_wh + lane;
    for (int k = 0; k < 3; k++) {
#pragma unroll 1
        for (int l = 0; l < 3; l++) {
            const int kl = k * 3 + l;
            const float* dwp = s_dw + kl * 64 + qw;
            const u32 dwh0 = packh2(dwp[g],     dwp[g]);
            const u32 dwh1 = packh2(dwp[g + 8], dwp[g + 8]);
            const int pixbase = k * 66 + l + qw;
            const uint4* wkl = wlane + (size_t)(kl * 4) * 128;

            // prologue: B for cq=0
            uint4 ba0 = __ldg(wkl);
            uint4 ba1 = __ldg(wkl + 32);
            uint4 ba2 = __ldg(wkl + 64);
            uint4 ba3 = __ldg(wkl + 96);

#pragma unroll
            for (int cq = 0; cq < 4; cq++) {
                // prefetch next cq's B under this cq's MMA burst
                uint4 nb0, nb1, nb2, nb3;
                if (cq < 3) {
                    const uint4* wn = wkl + (size_t)(cq + 1) * 128;
                    nb0 = __ldg(wn);
                    nb1 = __ldg(wn + 32);
                    nb2 = __ldg(wn + 64);
                    nb3 = __ldg(wn + 96);
                }

                const u32* pc  = s_imgh + (cq * 8 + t) * CPSTR + pixbase;
                const u32* pc4 = pc + 4 * CPSTR;    // channels +8
                u32 a0 = hmul2(pc [g],     dwh0);
                u32 a1 = hmul2(pc [g + 8], dwh1);
                u32 a2 = hmul2(pc4[g],     dwh0);
                u32 a3 = hmul2(pc4[g + 8], dwh1);

                MMA_F16(acc[0], a0, a1, a2, a3, ba0.x, ba0.y);
                MMA_F16(acc[1], a0, a1, a2, a3, ba0.z, ba0.w);
                MMA_F16(acc[2], a0, a1, a2, a3, ba1.x, ba1.y);
                MMA_F16(acc[3], a0, a1, a2, a3, ba1.z, ba1.w);
                MMA_F16(acc[4], a0, a1, a2, a3, ba2.x, ba2.y);
                MMA_F16(acc[5], a0, a1, a2, a3, ba2.z, ba2.w);
                MMA_F16(acc[6], a0, a1, a2, a3, ba3.x, ba3.y);
                MMA_F16(acc[7], a0, a1, a2, a3, ba3.z, ba3.w);

                if (cq < 3) { ba0 = nb0; ba1 = nb1; ba2 = nb2; ba3 = nb3; }
            }
        }
    }

    // ---- epilogue: bias + store (single output row p0) ----
    const int qq0 = qw + g;
#pragma unroll
    for (int nb = 0; nb < 8; nb++) {
        const int oc = nb * 8 + t * 2;
        const float bs0 = s_b[oc], bs1 = s_b[oc + 1];
        const size_t base =
            (((size_t)b * C_OUT + oc) * H_OUT + p0) * W_OUT + q0;
        if (qq0 < qcnt) {
            out[base + qq0]                         = acc[nb][0] + bs0;
            out[base + (size_t)H_OUT * W_OUT + qq0] = acc[nb][1] + bs1;
        }
        if (qq0 + 8 < qcnt) {
            out[base + qq0 + 8]                         = acc[nb][2] + bs0;
            out[base + (size_t)H_OUT * W_OUT + qq0 + 8] = acc[nb][3] + bs1;
        }
    }
}

extern "C" void kernel_launch(void* const* d_in, const int* in_sizes, int n_in,
                              void* d_out, int out_size) {
    const float* img    = nullptr;
    const float* depth  = nullptr;
    const float* weight = nullptr;
    const float* bias   = nullptr;

    for (int i = 0; i < n_in; i++) {
        switch (in_sizes[i]) {
            case 4 * C_IN * H_IN * W_IN: img    = (const float*)d_in[i]; break;
            case 4 * 1 * H_IN * W_IN:    depth  = (const float*)d_in[i]; break;
            case C_OUT * C_IN * 9:       weight = (const float*)d_in[i]; break;
            case C_OUT:                  bias   = (const float*)d_in[i]; break;
            default: break;
        }
    }

    cudaFuncSetAttribute(depthconv_mma,
                         cudaFuncAttributeMaxDynamicSharedMemorySize, SMEM_TOTAL);

    prep_w<<<(36 * 4 * 32 + 255) / 256, 256>>>(weight);
    depthconv_mma<<<NTILES, NTHREADS, SMEM_TOTAL>>>(img, depth, bias, (float*)d_out);
}